// round 5
// baseline (speedup 1.0000x reference)
#include <cuda_runtime.h>

#define Bdim 256
#define Sdim 512
#define Fdim 64
#define Hdim 128
#define BS   (Bdim * Sdim)
#define NBLK 128
#define NRS  16            // Whh k-rows resident in smem
#define KQ   28            // streamed quad groups: k = 16..127

__device__ float g_invDenom[Sdim];
__device__ float g_lossPartial[NBLK];
__device__ float g_WhhQ[KQ * 512 * 4];              // [(q4*512+j)*4+r] = Whh[j][16+4q4+r]
__device__ float g_gh[(size_t)BS * Hdim];           // gamma_h
__device__ float g_beta[(size_t)BS * Fdim];         // beta
__device__ float g_gml[(size_t)(BS / 2) * 1024];    // pair-interleaved ml@WihMask^T + bio

typedef unsigned long long u64;
__device__ __forceinline__ u64 pk2(float lo, float hi) {
    u64 r; asm("mov.b64 %0,{%1,%2};" : "=l"(r) : "r"(__float_as_uint(lo)), "r"(__float_as_uint(hi))); return r;
}
__device__ __forceinline__ void up2(u64 v, float& lo, float& hi) {
    unsigned a, b; asm("mov.b64 {%0,%1},%2;" : "=r"(a), "=r"(b) : "l"(v));
    lo = __uint_as_float(a); hi = __uint_as_float(b);
}
__device__ __forceinline__ u64 ff2(u64 a, u64 b, u64 c) {
    u64 d; asm("fma.rn.f32x2 %0,%1,%2,%3;" : "=l"(d) : "l"(a), "l"(b), "l"(c)); return d;
}
__device__ __forceinline__ float sigf(float v) { return 1.f / (1.f + expf(-v)); }

// ---------- per-step 1/(sum(m)+1e-5) ----------
__global__ void rits_denom(const float* __restrict__ m) {
    __shared__ float red[256];
    const int s = blockIdx.x, t = threadIdx.x;
    const float4* p = (const float4*)(m + (size_t)t * Sdim * Fdim + (size_t)s * Fdim);
    float sum = 0.f;
#pragma unroll
    for (int i = 0; i < 16; ++i) { float4 v = p[i]; sum += v.x + v.y + v.z + v.w; }
    red[t] = sum;
    __syncthreads();
    for (int off = 128; off > 0; off >>= 1) { if (t < off) red[t] += red[t + off]; __syncthreads(); }
    if (t == 0) g_invDenom[s] = 1.0f / (red[0] + 1e-5f);
}

// ---------- Whh streamed-tail swizzle ----------
__global__ void rits_whhq(const float* __restrict__ Whh) {
    const int i = blockIdx.x * 256 + threadIdx.x;
    if (i < KQ * 512 * 4) {
        const int r = i & 3, j = (i >> 2) & 511, q4 = i >> 11;
        g_WhhQ[i] = Whh[j * Hdim + NRS + 4 * q4 + r];
    }
}

// ---------- gamma_h ----------
__global__ __launch_bounds__(256) void rits_gh(const float* __restrict__ tt,
                                               const float* __restrict__ Wdh,
                                               const float* __restrict__ bdh) {
    __shared__ float w[Fdim * Hdim];   // [k*128+h]
    __shared__ float bb[Hdim], tl[2 * Fdim];
    const int t = threadIdx.x;
    for (int i = t; i < Fdim * Hdim; i += 256) { const int k = i >> 7, h = i & 127; w[i] = Wdh[h * Fdim + k]; }
    if (t < Hdim) bb[t] = bdh[t];
    __syncthreads();
    const int rr = t >> 7, h = t & 127;
    const size_t base = (size_t)blockIdx.x * 256;
    for (int it = 0; it < 128; ++it) {
        const size_t rs = base + it * 2;
        if (t < 128) { const int rw = t >> 6, f = t & 63; tl[t] = tt[(rs + rw) * Fdim + f]; }
        __syncthreads();
        float a0 = 0.f, a1 = 0.f;
        const float* tlr = tl + rr * 64;
#pragma unroll 8
        for (int k = 0; k < Fdim; k += 2) { a0 += tlr[k] * w[k * 128 + h]; a1 += tlr[k + 1] * w[(k + 1) * 128 + h]; }
        g_gh[(rs + rr) * Hdim + h] = expf(-fmaxf(a0 + a1 + bb[h], 0.f));
        __syncthreads();
    }
}

// ---------- beta ----------
__global__ __launch_bounds__(256) void rits_betak(const float* __restrict__ tt, const float* __restrict__ m,
                                                  const float* __restrict__ Wdm, const float* __restrict__ bdm,
                                                  const float* __restrict__ Wwc, const float* __restrict__ bwc) {
    __shared__ float w[128 * Fdim];    // [k*64+f] = Wwc[f][k]
    __shared__ float dwdm[64], cb[64], cw[64], gm[4 * 64], ms[4 * 64];
    const int t = threadIdx.x;
    for (int i = t; i < 128 * Fdim; i += 256) { const int k = i >> 6, f = i & 63; w[i] = Wwc[f * 128 + k]; }
    if (t < 64) { dwdm[t] = Wdm[t * Fdim + t]; cb[t] = bdm[t]; cw[t] = bwc[t]; }
    __syncthreads();
    const int r = t >> 6, f = t & 63;
    const size_t base = (size_t)blockIdx.x * 256;
    for (int it = 0; it < 64; ++it) {
        const size_t rs = base + it * 4 + r;
        const float tv = tt[rs * Fdim + f], mv = m[rs * Fdim + f];
        gm[t] = expf(-fmaxf(tv * dwdm[f] + cb[f], 0.f)); ms[t] = mv;
        __syncthreads();
        float a0 = cw[f], a1 = 0.f;
        const float* gr = gm + r * 64; const float* mr = ms + r * 64;
#pragma unroll 8
        for (int k = 0; k < 64; ++k) { a0 += gr[k] * w[k * 64 + f]; a1 += mr[k] * w[(64 + k) * 64 + f]; }
        g_beta[rs * Fdim + f] = a0 + a1;
        __syncthreads();
    }
}

// ---------- gml = ml @ WihMask^T + bih + bhh (pair-interleaved) ----------
#define GML_SMF (32768 + 512 + 128)
__global__ __launch_bounds__(256, 1) void rits_gml(const float* __restrict__ m, const float* __restrict__ Wih,
                                                   const float* __restrict__ bih, const float* __restrict__ bhh) {
    extern __shared__ float sg[];
    float* WT  = sg;            // [(k2*512+j)*2+r] = Wih[j][64+2k2+r]
    float* BIO = sg + 32768;
    float* MLP = sg + 33280;    // [2f+g]
    const int t = threadIdx.x;
    for (int i = t; i < 32768; i += 256) { const int r = i & 1, j = (i >> 1) & 511, k2 = i >> 10; WT[i] = Wih[j * 128 + 64 + 2 * k2 + r]; }
    for (int i = t; i < 512; i += 256) BIO[i] = bih[i] + bhh[i];
    __syncthreads();
    const int j0 = t, j1 = t + 256;
    const size_t p0 = (size_t)blockIdx.x * 256;
    for (int it = 0; it < 256; ++it) {
        const size_t p = p0 + it, bp = p >> 9, s = p & 511;
        if (t < 128) { const int g = t >> 6, f = t & 63; MLP[2 * f + g] = m[((2 * bp + g) * Sdim + s) * Fdim + f]; }
        __syncthreads();
        u64 a0 = pk2(BIO[j0], BIO[j0]), a1 = pk2(BIO[j1], BIO[j1]);
#pragma unroll 8
        for (int k2 = 0; k2 < 32; ++k2) {
            const float4 q = *(const float4*)(MLP + 4 * k2);
            const u64 b0 = pk2(q.x, q.y), b1 = pk2(q.z, q.w);
            const float2 w0 = *(const float2*)(WT + (k2 * 512 + j0) * 2);
            const float2 w1 = *(const float2*)(WT + (k2 * 512 + j1) * 2);
            a0 = ff2(pk2(w0.x, w0.x), b0, a0); a0 = ff2(pk2(w0.y, w0.y), b1, a0);
            a1 = ff2(pk2(w1.x, w1.x), b0, a1); a1 = ff2(pk2(w1.y, w1.y), b1, a1);
        }
        *(u64*)(g_gml + p * 1024 + 2 * j0) = a0;
        *(u64*)(g_gml + p * 1024 + 2 * j1) = a1;
        __syncthreads();
    }
}

// ---------- main sequential kernel ----------
#define M_WIHC 0
#define M_WHH0 32768
#define M_WTRT 40960
#define M_WFRT 49152
#define M_BTR  53248
#define M_BFR  53312
#define M_XL   53376
#define M_ML   53504
#define M_HP   53632
#define M_XCP  53888
#define M_CLCP 54016
#define M_XH   54144
#define M_ZH   54272
#define M_GT   54400
#define M_RED  55424
#define M_SMF  55680
#define M_SMB  (M_SMF * 4)

__global__ __launch_bounds__(256, 1) void rits_main(
    const float* __restrict__ x, const float* __restrict__ m,
    const float* __restrict__ Wtr, const float* __restrict__ btr,
    const float* __restrict__ Wfr, const float* __restrict__ bfr,
    const float* __restrict__ Wih, const float* __restrict__ Whh,
    float* __restrict__ out)
{
    extern __shared__ float sm[];
    const int t = threadIdx.x;
    const int b0 = blockIdx.x * 2;

    for (int i = t; i < 32768; i += 256) { const int r = i & 1, j = (i >> 1) & 511, k2 = i >> 10; sm[M_WIHC + i] = Wih[j * 128 + 2 * k2 + r]; }
    for (int i = t; i < 8192; i += 256)  { const int r = i & 3, j = (i >> 2) & 511, k4 = i >> 11; sm[M_WHH0 + i] = Whh[j * 128 + 4 * k4 + r]; }
    for (int i = t; i < 8192; i += 256)  { const int r = i & 1, f = (i >> 1) & 63, k2 = i >> 7; sm[M_WTRT + i] = Wtr[f * 128 + 2 * k2 + r]; }
    for (int i = t; i < 4096; i += 256)  { const int r = i & 1, f = (i >> 1) & 63, k2 = i >> 7; const int k = 2 * k2 + r; sm[M_WFRT + i] = (k == f) ? 0.f : Wfr[f * 64 + k]; }
    if (t < 64) { sm[M_BTR + t] = btr[t]; sm[M_BFR + t] = bfr[t]; }
    sm[M_HP + t] = 0.f;
    float c_reg = 0.f, loss = 0.f;
    __syncthreads();

    const int gE = t >> 6, fE = t & 63;          // phases A/C/D/E (t<128)
    const int gG = t >> 7, jG = t & 127;         // phases AB-h, G
    const int j0 = t, j1 = t + 256;              // phase F
    const float* gmlBase = g_gml + (size_t)blockIdx.x * Sdim * 1024;

    for (int s = 0; s < Sdim; ++s) {
        // A: inputs   B: h *= gamma_h
        if (t < 128) {
            const size_t idx = ((size_t)(b0 + gE) * Sdim + s) * Fdim + fE;
            sm[M_XL + t] = x[idx]; sm[M_ML + t] = m[idx];
        }
        sm[M_HP + 2 * jG + gG] *= g_gh[((size_t)(b0 + gG) * Sdim + s) * Hdim + jG];
        __syncthreads();

        // C: xl_hat, xl_c
        if (t < 128) {
            const float* hg = sm + M_HP + gE;
            float a0 = 0.f, a1 = 0.f;
#pragma unroll 8
            for (int k2 = 0; k2 < 64; ++k2) {
                const float2 w = *(const float2*)(sm + M_WTRT + (k2 * 64 + fE) * 2);
                a0 += w.x * hg[4 * k2]; a1 += w.y * hg[4 * k2 + 2];
            }
            const float xh = sm[M_BTR + fE] + a0 + a1;
            sm[M_XH + t] = xh;
            const float mv = sm[M_ML + t];
            sm[M_XCP + 2 * fE + gE] = mv * sm[M_XL + t] + (1.f - mv) * xh;
        }
        __syncthreads();

        // D: zl_hat
        if (t < 128) {
            const float* xg = sm + M_XCP + gE;
            float a0 = 0.f, a1 = 0.f;
#pragma unroll 8
            for (int k2 = 0; k2 < 32; ++k2) {
                const float2 w = *(const float2*)(sm + M_WFRT + (k2 * 64 + fE) * 2);
                a0 += w.x * xg[4 * k2]; a1 += w.y * xg[4 * k2 + 2];
            }
            sm[M_ZH + t] = sm[M_BFR + fE] + a0 + a1;
        }
        __syncthreads();

        // E: cl_hat, cl_c, output, loss
        if (t < 128) {
            const size_t idx = ((size_t)(b0 + gE) * Sdim + s) * Fdim + fE;
            const float bt = g_beta[idx];
            const float xh = sm[M_XH + t], zh = sm[M_ZH + t];
            const float xv = sm[M_XL + t], mv = sm[M_ML + t];
            const float ch = bt * zh + (1.f - bt) * xh;
            const float cc = mv * xv + (1.f - mv) * ch;
            sm[M_CLCP + 2 * fE + gE] = cc;
            out[idx] = cc;
            const float d1 = xv - xh, d2 = xv - zh, d3 = xv - ch;
            loss += mv * (d1 * d1 + d2 * d2 + d3 * d3) * g_invDenom[s];
        }
        __syncthreads();

        // F: gates
        {
            const float* gp = gmlBase + (size_t)s * 1024;
            u64 a0 = *(const u64*)(gp + 2 * j0);
            u64 a1 = *(const u64*)(gp + 2 * j1);
#pragma unroll 8
            for (int k2 = 0; k2 < 32; ++k2) {
                const float4 q = *(const float4*)(sm + M_CLCP + 4 * k2);
                const u64 b0p = pk2(q.x, q.y), b1p = pk2(q.z, q.w);
                const float2 w0 = *(const float2*)(sm + M_WIHC + (k2 * 512 + j0) * 2);
                const float2 w1 = *(const float2*)(sm + M_WIHC + (k2 * 512 + j1) * 2);
                a0 = ff2(pk2(w0.x, w0.x), b0p, a0); a0 = ff2(pk2(w0.y, w0.y), b1p, a0);
                a1 = ff2(pk2(w1.x, w1.x), b0p, a1); a1 = ff2(pk2(w1.y, w1.y), b1p, a1);
            }
#pragma unroll
            for (int k4 = 0; k4 < 4; ++k4) {
                const float4 h01 = *(const float4*)(sm + M_HP + 8 * k4);
                const float4 h23 = *(const float4*)(sm + M_HP + 8 * k4 + 4);
                const u64 p0 = pk2(h01.x, h01.y), p1 = pk2(h01.z, h01.w);
                const u64 p2 = pk2(h23.x, h23.y), p3 = pk2(h23.z, h23.w);
                const float4 w0 = *(const float4*)(sm + M_WHH0 + (k4 * 512 + j0) * 4);
                const float4 w1 = *(const float4*)(sm + M_WHH0 + (k4 * 512 + j1) * 4);
                a0 = ff2(pk2(w0.x, w0.x), p0, a0); a0 = ff2(pk2(w0.y, w0.y), p1, a0);
                a0 = ff2(pk2(w0.z, w0.z), p2, a0); a0 = ff2(pk2(w0.w, w0.w), p3, a0);
                a1 = ff2(pk2(w1.x, w1.x), p0, a1); a1 = ff2(pk2(w1.y, w1.y), p1, a1);
                a1 = ff2(pk2(w1.z, w1.z), p2, a1); a1 = ff2(pk2(w1.w, w1.w), p3, a1);
            }
#pragma unroll 4
            for (int q4 = 0; q4 < KQ; ++q4) {
                const float4 w0 = *(const float4*)(g_WhhQ + ((size_t)q4 * 512 + j0) * 4);
                const float4 w1 = *(const float4*)(g_WhhQ + ((size_t)q4 * 512 + j1) * 4);
                const float4 h01 = *(const float4*)(sm + M_HP + 32 + 8 * q4);
                const float4 h23 = *(const float4*)(sm + M_HP + 36 + 8 * q4);
                const u64 p0 = pk2(h01.x, h01.y), p1 = pk2(h01.z, h01.w);
                const u64 p2 = pk2(h23.x, h23.y), p3 = pk2(h23.z, h23.w);
                a0 = ff2(pk2(w0.x, w0.x), p0, a0); a0 = ff2(pk2(w0.y, w0.y), p1, a0);
                a0 = ff2(pk2(w0.z, w0.z), p2, a0); a0 = ff2(pk2(w0.w, w0.w), p3, a0);
                a1 = ff2(pk2(w1.x, w1.x), p0, a1); a1 = ff2(pk2(w1.y, w1.y), p1, a1);
                a1 = ff2(pk2(w1.z, w1.z), p2, a1); a1 = ff2(pk2(w1.w, w1.w), p3, a1);
            }
            float v0, v1;
            up2(a0, v0, v1); sm[M_GT + j0] = v0; sm[M_GT + 512 + j0] = v1;
            up2(a1, v0, v1); sm[M_GT + j1] = v0; sm[M_GT + 512 + j1] = v1;
        }
        __syncthreads();

        // G: LSTM update
        {
            const float* gg = sm + M_GT + gG * 512;
            const float iv = sigf(gg[jG]);
            const float fv = sigf(gg[128 + jG]);
            const float gv = tanhf(gg[256 + jG]);
            const float ov = sigf(gg[384 + jG]);
            c_reg = fv * c_reg + iv * gv;
            sm[M_HP + 2 * jG + gG] = ov * tanhf(c_reg);
        }
        __syncthreads();
    }

    sm[M_RED + t] = loss;
    __syncthreads();
    for (int off = 128; off > 0; off >>= 1) { if (t < off) sm[M_RED + t] += sm[M_RED + t + off]; __syncthreads(); }
    if (t == 0) g_lossPartial[blockIdx.x] = sm[M_RED];
}

__global__ void rits_loss_final(float* __restrict__ out, int out_size) {
    __shared__ float red[NBLK];
    const int t = threadIdx.x;
    red[t] = g_lossPartial[t];
    __syncthreads();
    for (int off = 64; off > 0; off >>= 1) { if (t < off) red[t] += red[t + off]; __syncthreads(); }
    const long long bsf = (long long)Bdim * Sdim * Fdim;
    if (t == 0 && (long long)out_size > bsf) out[bsf] = red[0] / (float)Sdim;
}

extern "C" void kernel_launch(void* const* d_in, const int* in_sizes, int n_in,
                              void* d_out, int out_size) {
    const float* x   = (const float*)d_in[0];
    const float* m   = (const float*)d_in[1];
    const float* tt  = (const float*)d_in[2];
    const float* Wdh = (const float*)d_in[3];
    const float* bdh = (const float*)d_in[4];
    const float* Wdm = (const float*)d_in[5];
    const float* bdm = (const float*)d_in[6];
    const float* Wtr = (const float*)d_in[7];
    const float* btr = (const float*)d_in[8];
    const float* Wfr = (const float*)d_in[9];
    const float* bfr = (const float*)d_in[10];
    const float* Wwc = (const float*)d_in[11];
    const float* bwc = (const float*)d_in[12];
    const float* Wih = (const float*)d_in[13];
    const float* Whh = (const float*)d_in[14];
    const float* bih = (const float*)d_in[15];
    const float* bhh = (const float*)d_in[16];
    float* out = (float*)d_out;

    cudaFuncSetAttribute(rits_gml, cudaFuncAttributeMaxDynamicSharedMemorySize, GML_SMF * 4);
    cudaFuncSetAttribute(rits_main, cudaFuncAttributeMaxDynamicSharedMemorySize, M_SMB);

    rits_denom<<<Sdim, 256>>>(m);
    rits_whhq<<<(KQ * 512 * 4 + 255) / 256, 256>>>(Whh);
    rits_gh<<<512, 256>>>(tt, Wdh, bdh);
    rits_betak<<<512, 256>>>(tt, m, Wdm, bdm, Wwc, bwc);
    rits_gml<<<256, 256, GML_SMF * 4>>>(m, Wih, bih, bhh);
    rits_main<<<NBLK, 256, M_SMB>>>(x, m, Wtr, btr, Wfr, bfr, Wih, Whh, out);
    rits_loss_final<<<1, NBLK>>>(out, out_size);
}

// round 6
// speedup vs baseline: 1.0677x; 1.0677x over previous
#include <cuda_runtime.h>

#define Bdim 256
#define Sdim 512
#define Fdim 64
#define Hdim 128
#define BS   (Bdim * Sdim)
#define NBLK 64            // 4 batch rows per block
#define KQ   28            // streamed Whh quad groups (k = 16..127)

__device__ float g_invDenom[Sdim];
__device__ float g_lossPartial[NBLK];
__device__ float g_WhhQ[KQ * 512 * 4];            // [(q*512+j)*4+r] = Whh[j][16+4q+r]
__device__ float g_gh[(size_t)BS * Hdim];         // gamma_h
__device__ float g_beta[(size_t)BS * Fdim];       // beta
__device__ float g_gml[(size_t)(BS / 2) * 1024];  // pair-interleaved ml@WihMask^T + bio

typedef unsigned long long u64;
__device__ __forceinline__ u64 pk2(float lo, float hi) {
    u64 r; asm("mov.b64 %0,{%1,%2};" : "=l"(r) : "r"(__float_as_uint(lo)), "r"(__float_as_uint(hi))); return r;
}
__device__ __forceinline__ void up2(u64 v, float& lo, float& hi) {
    unsigned a, b; asm("mov.b64 {%0,%1},%2;" : "=r"(a), "=r"(b) : "l"(v));
    lo = __uint_as_float(a); hi = __uint_as_float(b);
}
__device__ __forceinline__ u64 ff2(u64 a, u64 b, u64 c) {
    u64 d; asm("fma.rn.f32x2 %0,%1,%2,%3;" : "=l"(d) : "l"(a), "l"(b), "l"(c)); return d;
}
__device__ __forceinline__ float sigf(float v) { return 1.f / (1.f + expf(-v)); }

// ---------- per-step 1/(sum(m)+1e-5) ----------
__global__ void rits_denom(const float* __restrict__ m) {
    __shared__ float red[256];
    const int s = blockIdx.x, t = threadIdx.x;
    const float4* p = (const float4*)(m + (size_t)t * Sdim * Fdim + (size_t)s * Fdim);
    float sum = 0.f;
#pragma unroll
    for (int i = 0; i < 16; ++i) { float4 v = p[i]; sum += v.x + v.y + v.z + v.w; }
    red[t] = sum;
    __syncthreads();
    for (int off = 128; off > 0; off >>= 1) { if (t < off) red[t] += red[t + off]; __syncthreads(); }
    if (t == 0) g_invDenom[s] = 1.0f / (red[0] + 1e-5f);
}

// ---------- Whh streamed-tail swizzle (k = 16..127) ----------
__global__ void rits_whhq(const float* __restrict__ Whh) {
    const int i = blockIdx.x * 256 + threadIdx.x;
    if (i < KQ * 512 * 4) {
        const int r = i & 3, j = (i >> 2) & 511, q = i >> 11;
        g_WhhQ[i] = Whh[j * Hdim + 16 + 4 * q + r];
    }
}

// ---------- gamma_h (prefetched inputs) ----------
__global__ __launch_bounds__(256) void rits_gh(const float* __restrict__ tt,
                                               const float* __restrict__ Wdh,
                                               const float* __restrict__ bdh) {
    __shared__ float w[Fdim * Hdim];
    __shared__ float bb[Hdim], tl[128];
    const int t = threadIdx.x;
    for (int i = t; i < Fdim * Hdim; i += 256) { const int k = i >> 7, h = i & 127; w[i] = Wdh[h * Fdim + k]; }
    if (t < Hdim) bb[t] = bdh[t];
    const int rr = t >> 7, h = t & 127;
    const size_t base = (size_t)blockIdx.x * 256;
    float v = 0.f;
    if (t < 128) v = tt[(base + (t >> 6)) * Fdim + (t & 63)];
    __syncthreads();
    for (int it = 0; it < 128; ++it) {
        const size_t rs = base + it * 2;
        if (t < 128) tl[t] = v;
        __syncthreads();
        if (t < 128 && it < 127) v = tt[(rs + 2 + (t >> 6)) * Fdim + (t & 63)];
        float a0 = 0.f, a1 = 0.f;
        const float* tlr = tl + rr * 64;
#pragma unroll 8
        for (int k = 0; k < Fdim; k += 2) { a0 += tlr[k] * w[k * 128 + h]; a1 += tlr[k + 1] * w[(k + 1) * 128 + h]; }
        g_gh[(rs + rr) * Hdim + h] = expf(-fmaxf(a0 + a1 + bb[h], 0.f));
        __syncthreads();
    }
}

// ---------- beta (prefetched inputs) ----------
__global__ __launch_bounds__(256) void rits_betak(const float* __restrict__ tt, const float* __restrict__ m,
                                                  const float* __restrict__ Wdm, const float* __restrict__ bdm,
                                                  const float* __restrict__ Wwc, const float* __restrict__ bwc) {
    __shared__ float w[128 * Fdim];
    __shared__ float dwdm[64], cb[64], cw[64], gm[256], ms[256];
    const int t = threadIdx.x;
    for (int i = t; i < 128 * Fdim; i += 256) { const int k = i >> 6, f = i & 63; w[i] = Wwc[f * 128 + k]; }
    if (t < 64) { dwdm[t] = Wdm[t * Fdim + t]; cb[t] = bdm[t]; cw[t] = bwc[t]; }
    const int r = t >> 6, f = t & 63;
    const size_t base = (size_t)blockIdx.x * 256;
    float vt = tt[(base + r) * Fdim + f], vm = m[(base + r) * Fdim + f];
    __syncthreads();
    for (int it = 0; it < 64; ++it) {
        const size_t rs = base + it * 4 + r;
        gm[t] = expf(-fmaxf(vt * dwdm[f] + cb[f], 0.f)); ms[t] = vm;
        __syncthreads();
        if (it < 63) { vt = tt[(rs + 4) * Fdim + f]; vm = m[(rs + 4) * Fdim + f]; }
        float a0 = cw[f], a1 = 0.f;
        const float* gr = gm + r * 64; const float* mr = ms + r * 64;
#pragma unroll 8
        for (int k = 0; k < 64; ++k) { a0 += gr[k] * w[k * 64 + f]; a1 += mr[k] * w[(64 + k) * 64 + f]; }
        g_beta[rs * Fdim + f] = a0 + a1;
        __syncthreads();
    }
}

// ---------- gml = ml @ WihMask^T + bih + bhh (pair-interleaved, prefetched) ----------
#define GML_SMF (32768 + 512 + 128)
__global__ __launch_bounds__(256, 1) void rits_gml(const float* __restrict__ m, const float* __restrict__ Wih,
                                                   const float* __restrict__ bih, const float* __restrict__ bhh) {
    extern __shared__ float sg[];
    float* WT  = sg;
    float* BIO = sg + 32768;
    float* MLP = sg + 33280;
    const int t = threadIdx.x;
    for (int i = t; i < 32768; i += 256) { const int r = i & 1, j = (i >> 1) & 511, k2 = i >> 10; WT[i] = Wih[j * 128 + 64 + 2 * k2 + r]; }
    for (int i = t; i < 512; i += 256) BIO[i] = bih[i] + bhh[i];
    const int j0 = t, j1 = t + 256;
    const size_t p0 = (size_t)blockIdx.x * 256;
    float v = 0.f;
    if (t < 128) { const size_t p = p0, bp = p >> 9, s = p & 511; v = m[((2 * bp + (t >> 6)) * Sdim + s) * Fdim + (t & 63)]; }
    __syncthreads();
    for (int it = 0; it < 256; ++it) {
        const size_t p = p0 + it;
        if (t < 128) MLP[2 * (t & 63) + (t >> 6)] = v;
        __syncthreads();
        if (t < 128 && it < 255) { const size_t pn = p + 1, bp = pn >> 9, s = pn & 511; v = m[((2 * bp + (t >> 6)) * Sdim + s) * Fdim + (t & 63)]; }
        u64 a0 = pk2(BIO[j0], BIO[j0]), a1 = pk2(BIO[j1], BIO[j1]);
#pragma unroll 8
        for (int k2 = 0; k2 < 32; ++k2) {
            const float4 q = *(const float4*)(MLP + 4 * k2);
            const u64 b0 = pk2(q.x, q.y), b1 = pk2(q.z, q.w);
            const float2 w0 = *(const float2*)(WT + (k2 * 512 + j0) * 2);
            const float2 w1 = *(const float2*)(WT + (k2 * 512 + j1) * 2);
            a0 = ff2(pk2(w0.x, w0.x), b0, a0); a0 = ff2(pk2(w0.y, w0.y), b1, a0);
            a1 = ff2(pk2(w1.x, w1.x), b0, a1); a1 = ff2(pk2(w1.y, w1.y), b1, a1);
        }
        *(u64*)(g_gml + p * 1024 + 2 * j0) = a0;
        *(u64*)(g_gml + p * 1024 + 2 * j1) = a1;
        __syncthreads();
    }
}

// ---------- main sequential kernel (G=4 rows/block) ----------
#define M_WIHQ 0        // 32768: [q<16][j][4] = Wih[j][4q+r]
#define M_WHHR 32768    // 8192:  [q<4][j][4]  = Whh[j][4q+r]
#define M_WTRT 40960    // 8192:  [k][f] = Wtr[f][k]
#define M_WFRT 49152    // 4096:  [k][f] = Wfr_m[f][k]
#define M_ACT  53248    // 768: clc at [4f+r] (f<64), h at [256+4j+r] (j<128)
#define M_XC   54016    // 256: [r*64+k]
#define M_GT   54272    // 2048: [r*512+g]
#define M_BTR  56320    // 64
#define M_BFR  56384    // 64
#define M_RED  56448    // 256
#define M_SMF  56704
#define M_SMB  (M_SMF * 4)   // 226,816 B

#define FQ4(W0, W1, KB) do {                                                   \
    const float4 w0_ = (W0); const float4 w1_ = (W1);                          \
    { const ulonglong2 av = *(const ulonglong2*)(sm + M_ACT + (KB));           \
      const u64 d0 = pk2(w0_.x, w0_.x), d1 = pk2(w1_.x, w1_.x);                \
      a00 = ff2(d0, av.x, a00); a01 = ff2(d0, av.y, a01);                      \
      a10 = ff2(d1, av.x, a10); a11 = ff2(d1, av.y, a11); }                    \
    { const ulonglong2 av = *(const ulonglong2*)(sm + M_ACT + (KB) + 4);       \
      const u64 d0 = pk2(w0_.y, w0_.y), d1 = pk2(w1_.y, w1_.y);                \
      a00 = ff2(d0, av.x, a00); a01 = ff2(d0, av.y, a01);                      \
      a10 = ff2(d1, av.x, a10); a11 = ff2(d1, av.y, a11); }                    \
    { const ulonglong2 av = *(const ulonglong2*)(sm + M_ACT + (KB) + 8);       \
      const u64 d0 = pk2(w0_.z, w0_.z), d1 = pk2(w1_.z, w1_.z);                \
      a00 = ff2(d0, av.x, a00); a01 = ff2(d0, av.y, a01);                      \
      a10 = ff2(d1, av.x, a10); a11 = ff2(d1, av.y, a11); }                    \
    { const ulonglong2 av = *(const ulonglong2*)(sm + M_ACT + (KB) + 12);      \
      const u64 d0 = pk2(w0_.w, w0_.w), d1 = pk2(w1_.w, w1_.w);                \
      a00 = ff2(d0, av.x, a00); a01 = ff2(d0, av.y, a01);                      \
      a10 = ff2(d1, av.x, a10); a11 = ff2(d1, av.y, a11); }                    \
} while (0)

__global__ __launch_bounds__(256, 1) void rits_main(
    const float* __restrict__ x, const float* __restrict__ m,
    const float* __restrict__ Wtr, const float* __restrict__ btr,
    const float* __restrict__ Wfr, const float* __restrict__ bfr,
    const float* __restrict__ Wih, const float* __restrict__ Whh,
    float* __restrict__ out)
{
    extern __shared__ float sm[];
    const int t = threadIdx.x;
    const int b0 = blockIdx.x * 4;

    for (int i = t; i < 32768; i += 256) { const int r = i & 3, j = (i >> 2) & 511, q = i >> 11; sm[M_WIHQ + i] = Wih[j * 128 + 4 * q + r]; }
    for (int i = t; i < 8192; i += 256)  { const int r = i & 3, j = (i >> 2) & 511, q = i >> 11; sm[M_WHHR + i] = Whh[j * 128 + 4 * q + r]; }
    for (int i = t; i < 8192; i += 256)  { const int k = i >> 6, f = i & 63; sm[M_WTRT + i] = Wtr[f * 128 + k]; }
    for (int i = t; i < 4096; i += 256)  { const int k = i >> 6, f = i & 63; sm[M_WFRT + i] = (k == f) ? 0.f : Wfr[f * 64 + k]; }
    if (t < 64) { sm[M_BTR + t] = btr[t]; sm[M_BFR + t] = bfr[t]; }
    for (int i = t; i < 768; i += 256) sm[M_ACT + i] = 0.f;
    float c1 = 0.f, c2 = 0.f, loss = 0.f;

    const int rE = t >> 6, fE = t & 63;     // C/D/E role
    const int j0 = t, j1 = t + 256;         // F role
    const int rG = t >> 7, jG = t & 127;    // G role: states (rG,jG),(rG+2,jG)

    const float* gmlA = g_gml + (size_t)(2 * blockIdx.x) * Sdim * 1024;
    const float* gmlB = gmlA + (size_t)Sdim * 1024;

    // prologue prefetch (s = 0)
    size_t idxP = ((size_t)(b0 + rE) * Sdim) * Fdim + fE;
    float cx = x[idxP], cm = m[idxP], cbeta = g_beta[idxP];
    u64 cg00 = *(const u64*)(gmlA + 2 * j0), cg01 = *(const u64*)(gmlB + 2 * j0);
    u64 cg10 = *(const u64*)(gmlA + 2 * j1), cg11 = *(const u64*)(gmlB + 2 * j1);
    __syncthreads();

    for (int s = 0; s < Sdim; ++s) {
        const int sn = (s < Sdim - 1) ? s + 1 : s;
        // early prefetches: gh for THIS step's G (gamma(s+1)); next-step x/m/beta/gml
        const float gh1 = g_gh[((size_t)(b0 + rG) * Sdim + sn) * Hdim + jG];
        const float gh2 = g_gh[((size_t)(b0 + 2 + rG) * Sdim + sn) * Hdim + jG];
        const float cInv = g_invDenom[s];
        const size_t idxN = ((size_t)(b0 + rE) * Sdim + sn) * Fdim + fE;
        const float nx = x[idxN], nm = m[idxN], nbeta = g_beta[idxN];
        const float* gA = gmlA + (size_t)sn * 1024;
        const float* gB = gmlB + (size_t)sn * 1024;
        const u64 ng00 = *(const u64*)(gA + 2 * j0), ng01 = *(const u64*)(gB + 2 * j0);
        const u64 ng10 = *(const u64*)(gA + 2 * j1), ng11 = *(const u64*)(gB + 2 * j1);

        // C: xl_hat, xl_c
        float xh;
        {
            float a0 = 0.f, a1 = 0.f;
            const float* hr = sm + M_ACT + 256 + rE;
#pragma unroll 8
            for (int k = 0; k < Hdim; k += 2) {
                a0 += hr[4 * k] * sm[M_WTRT + k * 64 + fE];
                a1 += hr[4 * (k + 1)] * sm[M_WTRT + (k + 1) * 64 + fE];
            }
            xh = sm[M_BTR + fE] + a0 + a1;
            sm[M_XC + rE * 64 + fE] = cm * cx + (1.f - cm) * xh;
        }
        __syncthreads();

        // D+E: zl_hat, cl_hat, cl_c, output, loss
        {
            float z0 = 0.f, z1 = 0.f;
            const float* xr = sm + M_XC + rE * 64;
#pragma unroll 8
            for (int k = 0; k < Fdim; k += 2) {
                z0 += xr[k] * sm[M_WFRT + k * 64 + fE];
                z1 += xr[k + 1] * sm[M_WFRT + (k + 1) * 64 + fE];
            }
            const float zh = sm[M_BFR + fE] + z0 + z1;
            const float ch = cbeta * zh + (1.f - cbeta) * xh;
            const float cc = cm * cx + (1.f - cm) * ch;
            sm[M_ACT + 4 * fE + rE] = cc;
            out[((size_t)(b0 + rE) * Sdim + s) * Fdim + fE] = cc;
            const float d1 = cx - xh, d2 = cx - zh, d3 = cx - ch;
            loss += cm * (d1 * d1 + d2 * d2 + d3 * d3) * cInv;
        }
        __syncthreads();

        // F: gates (rows-packed f32x2; quad-k over clc(16q) + h resident(4q) + h streamed(28q))
        {
            u64 a00 = cg00, a01 = cg01, a10 = cg10, a11 = cg11;
#pragma unroll 8
            for (int q = 0; q < 16; ++q)
                FQ4(*(const float4*)(sm + M_WIHQ + (q * 512 + j0) * 4),
                    *(const float4*)(sm + M_WIHQ + (q * 512 + j1) * 4), 16 * q);
#pragma unroll
            for (int q = 0; q < 4; ++q)
                FQ4(*(const float4*)(sm + M_WHHR + (q * 512 + j0) * 4),
                    *(const float4*)(sm + M_WHHR + (q * 512 + j1) * 4), 256 + 16 * q);
#pragma unroll 4
            for (int q = 0; q < KQ; ++q)
                FQ4(*(const float4*)(g_WhhQ + ((size_t)q * 512 + j0) * 4),
                    *(const float4*)(g_WhhQ + ((size_t)q * 512 + j1) * 4), 320 + 16 * q);
            float v0, v1;
            up2(a00, v0, v1); sm[M_GT + j0] = v0; sm[M_GT + 512 + j0] = v1;
            up2(a01, v0, v1); sm[M_GT + 1024 + j0] = v0; sm[M_GT + 1536 + j0] = v1;
            up2(a10, v0, v1); sm[M_GT + j1] = v0; sm[M_GT + 512 + j1] = v1;
            up2(a11, v0, v1); sm[M_GT + 1024 + j1] = v0; sm[M_GT + 1536 + j1] = v1;
        }
        __syncthreads();

        // G: LSTM update + apply gamma_h(s+1) to h
        {
            const float* g0 = sm + M_GT + rG * 512;
            const float iv0 = sigf(g0[jG]);
            const float fv0 = sigf(g0[128 + jG]);
            const float gv0 = tanhf(g0[256 + jG]);
            const float ov0 = sigf(g0[384 + jG]);
            c1 = fv0 * c1 + iv0 * gv0;
            sm[M_ACT + 256 + 4 * jG + rG] = ov0 * tanhf(c1) * gh1;
            const float* g1 = sm + M_GT + (2 + rG) * 512;
            const float iv1 = sigf(g1[jG]);
            const float fv1 = sigf(g1[128 + jG]);
            const float gv1 = tanhf(g1[256 + jG]);
            const float ov1 = sigf(g1[384 + jG]);
            c2 = fv1 * c2 + iv1 * gv1;
            sm[M_ACT + 256 + 4 * jG + 2 + rG] = ov1 * tanhf(c2) * gh2;
        }
        __syncthreads();

        cx = nx; cm = nm; cbeta = nbeta;
        cg00 = ng00; cg01 = ng01; cg10 = ng10; cg11 = ng11;
    }

    sm[M_RED + t] = loss;
    __syncthreads();
    for (int off = 128; off > 0; off >>= 1) { if (t < off) sm[M_RED + t] += sm[M_RED + t + off]; __syncthreads(); }
    if (t == 0) g_lossPartial[blockIdx.x] = sm[M_RED];
}

__global__ void rits_loss_final(float* __restrict__ out, int out_size) {
    __shared__ float red[NBLK];
    const int t = threadIdx.x;
    red[t] = g_lossPartial[t];
    __syncthreads();
    for (int off = NBLK / 2; off > 0; off >>= 1) { if (t < off) red[t] += red[t + off]; __syncthreads(); }
    const long long bsf = (long long)Bdim * Sdim * Fdim;
    if (t == 0 && (long long)out_size > bsf) out[bsf] = red[0] / (float)Sdim;
}

extern "C" void kernel_launch(void* const* d_in, const int* in_sizes, int n_in,
                              void* d_out, int out_size) {
    const float* x   = (const float*)d_in[0];
    const float* m   = (const float*)d_in[1];
    const float* tt  = (const float*)d_in[2];
    const float* Wdh = (const float*)d_in[3];
    const float* bdh = (const float*)d_in[4];
    const float* Wdm = (const float*)d_in[5];
    const float* bdm = (const float*)d_in[6];
    const float* Wtr = (const float*)d_in[7];
    const float* btr = (const float*)d_in[8];
    const float* Wfr = (const float*)d_in[9];
    const float* bfr = (const float*)d_in[10];
    const float* Wwc = (const float*)d_in[11];
    const float* bwc = (const float*)d_in[12];
    const float* Wih = (const float*)d_in[13];
    const float* Whh = (const float*)d_in[14];
    const float* bih = (const float*)d_in[15];
    const float* bhh = (const float*)d_in[16];
    float* out = (float*)d_out;

    cudaFuncSetAttribute(rits_gml, cudaFuncAttributeMaxDynamicSharedMemorySize, GML_SMF * 4);
    cudaFuncSetAttribute(rits_main, cudaFuncAttributeMaxDynamicSharedMemorySize, M_SMB);

    rits_denom<<<Sdim, 256>>>(m);
    rits_whhq<<<(KQ * 512 * 4 + 255) / 256, 256>>>(Whh);
    rits_gh<<<512, 256>>>(tt, Wdh, bdh);
    rits_betak<<<512, 256>>>(tt, m, Wdm, bdm, Wwc, bwc);
    rits_gml<<<256, 256, GML_SMF * 4>>>(m, Wih, bih, bhh);
    rits_main<<<NBLK, 256, M_SMB>>>(x, m, Wtr, btr, Wfr, bfr, Wih, Whh, out);
    rits_loss_final<<<1, NBLK>>>(out, out_size);
}

// round 7
// speedup vs baseline: 1.1799x; 1.1051x over previous
#include <cuda_runtime.h>

#define Bdim 256
#define Sdim 512
#define Fdim 64
#define Hdim 128
#define BS   (Bdim * Sdim)
#define NBLK 64            // 4 batch rows per block
#define KQ   28            // streamed Whh quad groups (k = 16..127)

__device__ float g_invDenom[Sdim];
__device__ float g_lossPartial[NBLK];
__device__ float g_WhhQ[KQ * 512 * 4];            // [(q*512+j)*4+r] = Whh[j][16+4q+r]
__device__ float g_gh[(size_t)BS * Hdim];         // gamma_h
__device__ float g_beta[(size_t)BS * Fdim];       // beta
__device__ float g_gml[(size_t)BS * 512];         // plain [b][s][j]: ml@WihMask^T + bio

typedef unsigned long long u64;
__device__ __forceinline__ u64 pk2(float lo, float hi) {
    u64 r; asm("mov.b64 %0,{%1,%2};" : "=l"(r) : "r"(__float_as_uint(lo)), "r"(__float_as_uint(hi))); return r;
}
__device__ __forceinline__ void up2(u64 v, float& lo, float& hi) {
    unsigned a, b; asm("mov.b64 {%0,%1},%2;" : "=r"(a), "=r"(b) : "l"(v));
    lo = __uint_as_float(a); hi = __uint_as_float(b);
}
__device__ __forceinline__ u64 ff2(u64 a, u64 b, u64 c) {
    u64 d; asm("fma.rn.f32x2 %0,%1,%2,%3;" : "=l"(d) : "l"(a), "l"(b), "l"(c)); return d;
}
__device__ __forceinline__ float sigf(float v) { return 1.f / (1.f + expf(-v)); }

// ---------- per-step 1/(sum(m)+1e-5) ----------
__global__ void rits_denom(const float* __restrict__ m) {
    __shared__ float red[256];
    const int s = blockIdx.x, t = threadIdx.x;
    const float4* p = (const float4*)(m + (size_t)t * Sdim * Fdim + (size_t)s * Fdim);
    float sum = 0.f;
#pragma unroll
    for (int i = 0; i < 16; ++i) { float4 v = p[i]; sum += v.x + v.y + v.z + v.w; }
    red[t] = sum;
    __syncthreads();
    for (int off = 128; off > 0; off >>= 1) { if (t < off) red[t] += red[t + off]; __syncthreads(); }
    if (t == 0) g_invDenom[s] = 1.0f / (red[0] + 1e-5f);
}

// ---------- Whh streamed-tail swizzle (k = 16..127) ----------
__global__ void rits_whhq(const float* __restrict__ Whh) {
    const int i = blockIdx.x * 256 + threadIdx.x;
    if (i < KQ * 512 * 4) {
        const int r = i & 3, j = (i >> 2) & 511, q = i >> 11;
        g_WhhQ[i] = Whh[j * Hdim + 16 + 4 * q + r];
    }
}

// ---------- gamma_h (double-buffered, grid 1024) ----------
__global__ __launch_bounds__(256) void rits_gh(const float* __restrict__ tt,
                                               const float* __restrict__ Wdh,
                                               const float* __restrict__ bdh) {
    __shared__ float w[Fdim * Hdim];
    __shared__ float bb[Hdim], tl[2][128];
    const int t = threadIdx.x;
    for (int i = t; i < Fdim * Hdim; i += 256) { const int k = i >> 7, h = i & 127; w[i] = Wdh[h * Fdim + k]; }
    if (t < Hdim) bb[t] = bdh[t];
    const int rr = t >> 7, h = t & 127;
    const size_t base = (size_t)blockIdx.x * 128;
    float v = 0.f;
    if (t < 128) v = tt[(base + (t >> 6)) * Fdim + (t & 63)];
    __syncthreads();
    for (int it = 0; it < 64; ++it) {
        const size_t rs = base + it * 2;
        if (t < 128) tl[it & 1][t] = v;
        __syncthreads();
        if (t < 128 && it < 63) v = tt[(rs + 2 + (t >> 6)) * Fdim + (t & 63)];
        float a0 = 0.f, a1 = 0.f;
        const float* tlr = tl[it & 1] + rr * 64;
#pragma unroll 8
        for (int k = 0; k < Fdim; k += 2) { a0 += tlr[k] * w[k * 128 + h]; a1 += tlr[k + 1] * w[(k + 1) * 128 + h]; }
        g_gh[(rs + rr) * Hdim + h] = expf(-fmaxf(a0 + a1 + bb[h], 0.f));
    }
}

// ---------- beta (double-buffered, grid 1024) ----------
__global__ __launch_bounds__(256) void rits_betak(const float* __restrict__ tt, const float* __restrict__ m,
                                                  const float* __restrict__ Wdm, const float* __restrict__ bdm,
                                                  const float* __restrict__ Wwc, const float* __restrict__ bwc) {
    __shared__ float w[128 * Fdim];
    __shared__ float dwdm[64], cb[64], cw[64], gm[2][256], ms[2][256];
    const int t = threadIdx.x;
    for (int i = t; i < 128 * Fdim; i += 256) { const int k = i >> 6, f = i & 63; w[i] = Wwc[f * 128 + k]; }
    if (t < 64) { dwdm[t] = Wdm[t * Fdim + t]; cb[t] = bdm[t]; cw[t] = bwc[t]; }
    const int r = t >> 6, f = t & 63;
    const size_t base = (size_t)blockIdx.x * 128;
    float vt = tt[(base + r) * Fdim + f], vm = m[(base + r) * Fdim + f];
    __syncthreads();
    for (int it = 0; it < 32; ++it) {
        const size_t rs = base + it * 4 + r;
        const int bf = it & 1;
        gm[bf][t] = expf(-fmaxf(vt * dwdm[f] + cb[f], 0.f)); ms[bf][t] = vm;
        __syncthreads();
        if (it < 31) { vt = tt[(rs + 4) * Fdim + f]; vm = m[(rs + 4) * Fdim + f]; }
        float a0 = cw[f], a1 = 0.f;
        const float* gr = gm[bf] + r * 64; const float* mr = ms[bf] + r * 64;
#pragma unroll 8
        for (int k = 0; k < 64; ++k) { a0 += gr[k] * w[k * 64 + f]; a1 += mr[k] * w[(64 + k) * 64 + f]; }
        g_beta[rs * Fdim + f] = a0 + a1;
    }
}

// ---------- gml = ml @ WihMask^T + bih + bhh (4 rows/iter, double-buffered) ----------
#define GML_SMF (32768 + 512 + 512)
__global__ __launch_bounds__(256, 1) void rits_gml(const float* __restrict__ m, const float* __restrict__ Wih,
                                                   const float* __restrict__ bih, const float* __restrict__ bhh) {
    extern __shared__ float sg[];
    float* WT  = sg;            // [(k2*512+j)*2+r] = Wih[j][64+2k2+r]
    float* BIO = sg + 32768;
    float* MLP = sg + 33280;    // [2 buf][2 pair][128]
    const int t = threadIdx.x;
    for (int i = t; i < 32768; i += 256) { const int r = i & 1, j = (i >> 1) & 511, k2 = i >> 10; WT[i] = Wih[j * 128 + 64 + 2 * k2 + r]; }
    for (int i = t; i < 512; i += 256) BIO[i] = bih[i] + bhh[i];
    const int j0 = t, j1 = t + 256;
    const int pr = t >> 7, gq = (t >> 6) & 1, f = t & 63;
    const size_t base = (size_t)blockIdx.x * 256;   // 256 p per block (2 per iter)
    float v;
    { const size_t p0 = base; const size_t bp = p0 >> 9; const int s0 = (int)(p0 & 511);
      v = m[((2 * bp + gq) * Sdim + s0 + pr) * Fdim + f]; }
    __syncthreads();
    for (int it = 0; it < 128; ++it) {
        const size_t p0 = base + 2 * it; const size_t bp = p0 >> 9; const int s0 = (int)(p0 & 511);
        float* B = MLP + (it & 1) * 256;
        B[pr * 128 + 2 * f + gq] = v;
        __syncthreads();
        if (it < 127) { const size_t pn = base + 2 * (it + 1); const size_t bpn = pn >> 9; const int sn0 = (int)(pn & 511);
            v = m[((2 * bpn + gq) * Sdim + sn0 + pr) * Fdim + f]; }
        const float bj0 = BIO[j0], bj1 = BIO[j1];
        u64 a00 = pk2(bj0, bj0), a01 = pk2(bj0, bj0);
        u64 a10 = pk2(bj1, bj1), a11 = pk2(bj1, bj1);
        const float* B0 = B; const float* B1 = B + 128;
#pragma unroll 8
        for (int k2 = 0; k2 < 32; ++k2) {
            const float2 w0 = *(const float2*)(WT + (k2 * 512 + j0) * 2);
            const float2 w1 = *(const float2*)(WT + (k2 * 512 + j1) * 2);
            const ulonglong2 q0 = *(const ulonglong2*)(B0 + 4 * k2);
            const ulonglong2 q1 = *(const ulonglong2*)(B1 + 4 * k2);
            const u64 wx0 = pk2(w0.x, w0.x), wy0 = pk2(w0.y, w0.y);
            const u64 wx1 = pk2(w1.x, w1.x), wy1 = pk2(w1.y, w1.y);
            a00 = ff2(wx0, q0.x, a00); a00 = ff2(wy0, q0.y, a00);
            a01 = ff2(wx0, q1.x, a01); a01 = ff2(wy0, q1.y, a01);
            a10 = ff2(wx1, q0.x, a10); a10 = ff2(wy1, q0.y, a10);
            a11 = ff2(wx1, q1.x, a11); a11 = ff2(wy1, q1.y, a11);
        }
        float lo, hi;
        up2(a00, lo, hi);
        g_gml[((2 * bp + 0) * Sdim + s0) * 512 + j0] = lo;
        g_gml[((2 * bp + 1) * Sdim + s0) * 512 + j0] = hi;
        up2(a01, lo, hi);
        g_gml[((2 * bp + 0) * Sdim + s0 + 1) * 512 + j0] = lo;
        g_gml[((2 * bp + 1) * Sdim + s0 + 1) * 512 + j0] = hi;
        up2(a10, lo, hi);
        g_gml[((2 * bp + 0) * Sdim + s0) * 512 + j1] = lo;
        g_gml[((2 * bp + 1) * Sdim + s0) * 512 + j1] = hi;
        up2(a11, lo, hi);
        g_gml[((2 * bp + 0) * Sdim + s0 + 1) * 512 + j1] = lo;
        g_gml[((2 * bp + 1) * Sdim + s0 + 1) * 512 + j1] = hi;
    }
}

// ---------- main sequential kernel (G=4, k-pair packed f32x2) ----------
#define M_WIHQ 0        // 32768: [q<16][j][4] = Wih[j][4q+r]
#define M_WHHR 32768    // 8192:  [q<4][j][4]  = Whh[j][4q+r]
#define M_WTRQ 40960    // 8192:  [q<32][f][4] = Wtr[f][4q+r]
#define M_WFRQ 49152    // 4096:  [q<16][f][4] = Wfr_m[f][4q+r]
#define M_HR   53248    // 512:  hRow[4][128]
#define M_XC   53760    // 256:  xcRow[4][64]
#define M_CLC  54016    // 256:  clcRow[4][64]
#define M_GT   54272    // 2048: gates[4][512]
#define M_BTR  56320
#define M_BFR  56384
#define M_RED  56448
#define M_SMF  56704
#define M_SMB  (M_SMF * 4)   // 226,816 B

// one quad-k group: 2 weight ulonglong2 + 4 act rows; 16 ff2, 0 packing
#define FSTEP(WP0, WP1, AP, STR) do {                                   \
    const ulonglong2 w0_ = *(const ulonglong2*)(WP0);                   \
    const ulonglong2 w1_ = *(const ulonglong2*)(WP1);                   \
    { const ulonglong2 a_ = *(const ulonglong2*)(AP);                   \
      A00 = ff2(w0_.x, a_.x, A00); A00 = ff2(w0_.y, a_.y, A00);         \
      A10 = ff2(w1_.x, a_.x, A10); A10 = ff2(w1_.y, a_.y, A10); }       \
    { const ulonglong2 a_ = *(const ulonglong2*)((AP) + (STR));         \
      A01 = ff2(w0_.x, a_.x, A01); A01 = ff2(w0_.y, a_.y, A01);         \
      A11 = ff2(w1_.x, a_.x, A11); A11 = ff2(w1_.y, a_.y, A11); }       \
    { const ulonglong2 a_ = *(const ulonglong2*)((AP) + 2 * (STR));     \
      A02 = ff2(w0_.x, a_.x, A02); A02 = ff2(w0_.y, a_.y, A02);         \
      A12 = ff2(w1_.x, a_.x, A12); A12 = ff2(w1_.y, a_.y, A12); }       \
    { const ulonglong2 a_ = *(const ulonglong2*)((AP) + 3 * (STR));     \
      A03 = ff2(w0_.x, a_.x, A03); A03 = ff2(w0_.y, a_.y, A03);         \
      A13 = ff2(w1_.x, a_.x, A13); A13 = ff2(w1_.y, a_.y, A13); }       \
} while (0)

__global__ __launch_bounds__(256, 1) void rits_main(
    const float* __restrict__ x, const float* __restrict__ m,
    const float* __restrict__ Wtr, const float* __restrict__ btr,
    const float* __restrict__ Wfr, const float* __restrict__ bfr,
    const float* __restrict__ Wih, const float* __restrict__ Whh,
    float* __restrict__ out)
{
    extern __shared__ float sm[];
    const int t = threadIdx.x;
    const int b0 = blockIdx.x * 4;

    for (int i = t; i < 32768; i += 256) { const int r = i & 3, j = (i >> 2) & 511, q = i >> 11; sm[M_WIHQ + i] = Wih[j * 128 + 4 * q + r]; }
    for (int i = t; i < 8192; i += 256)  { const int r = i & 3, j = (i >> 2) & 511, q = i >> 11; sm[M_WHHR + i] = Whh[j * 128 + 4 * q + r]; }
    for (int i = t; i < 8192; i += 256)  { const int r = i & 3, f = (i >> 2) & 63, q = i >> 8; sm[M_WTRQ + i] = Wtr[f * 128 + 4 * q + r]; }
    for (int i = t; i < 4096; i += 256)  { const int r = i & 3, f = (i >> 2) & 63, q = i >> 8; const int k = 4 * q + r; sm[M_WFRQ + i] = (k == f) ? 0.f : Wfr[f * 64 + k]; }
    if (t < 64) { sm[M_BTR + t] = btr[t]; sm[M_BFR + t] = bfr[t]; }
    for (int i = t; i < 512; i += 256) sm[M_HR + i] = 0.f;
    float c1 = 0.f, c2 = 0.f, loss = 0.f;

    const int rE = t >> 6, fE = t & 63;     // C/D/E role (4 rows x 64 f)
    const int j0 = t, j1 = t + 256;         // F role
    const int rG = t >> 7, jG = t & 127;    // G role

    // prologue prefetch (s = 0)
    size_t idxP = ((size_t)(b0 + rE) * Sdim) * Fdim + fE;
    float cx = x[idxP], cm = m[idxP], cbeta = g_beta[idxP];
    float cgml[8];
#pragma unroll
    for (int r = 0; r < 4; ++r) {
        cgml[r]     = g_gml[((size_t)(b0 + r) * Sdim) * 512 + j0];
        cgml[4 + r] = g_gml[((size_t)(b0 + r) * Sdim) * 512 + j1];
    }
    __syncthreads();

    for (int s = 0; s < Sdim; ++s) {
        const int sn = (s < Sdim - 1) ? s + 1 : s;
        // prefetch: gamma_h(s+1) for G; next-step x/m/beta/gml
        const float gh1 = g_gh[((size_t)(b0 + rG) * Sdim + sn) * Hdim + jG];
        const float gh2 = g_gh[((size_t)(b0 + 2 + rG) * Sdim + sn) * Hdim + jG];
        const float cInv = g_invDenom[s];
        const size_t idxN = ((size_t)(b0 + rE) * Sdim + sn) * Fdim + fE;
        const float nx = x[idxN], nm = m[idxN], nbeta = g_beta[idxN];
        float ngml[8];
#pragma unroll
        for (int r = 0; r < 4; ++r) {
            ngml[r]     = g_gml[((size_t)(b0 + r) * Sdim + sn) * 512 + j0];
            ngml[4 + r] = g_gml[((size_t)(b0 + r) * Sdim + sn) * 512 + j1];
        }

        // C: xl_hat = h @ Wtr^T + btr ; xl_c
        float xh;
        {
            u64 acc = 0ULL;
            const float* hr = sm + M_HR + rE * 128;
#pragma unroll 8
            for (int q = 0; q < 32; ++q) {
                const ulonglong2 w = *(const ulonglong2*)(sm + M_WTRQ + (q * 64 + fE) * 4);
                const ulonglong2 a = *(const ulonglong2*)(hr + 4 * q);
                acc = ff2(w.x, a.x, acc); acc = ff2(w.y, a.y, acc);
            }
            float lo, hi; up2(acc, lo, hi);
            xh = sm[M_BTR + fE] + lo + hi;
            sm[M_XC + rE * 64 + fE] = cm * cx + (1.f - cm) * xh;
        }
        __syncthreads();

        // D+E: zl_hat, cl_hat, cl_c, output, loss
        {
            u64 acc = 0ULL;
            const float* xr = sm + M_XC + rE * 64;
#pragma unroll
            for (int q = 0; q < 16; ++q) {
                const ulonglong2 w = *(const ulonglong2*)(sm + M_WFRQ + (q * 64 + fE) * 4);
                const ulonglong2 a = *(const ulonglong2*)(xr + 4 * q);
                acc = ff2(w.x, a.x, acc); acc = ff2(w.y, a.y, acc);
            }
            float lo, hi; up2(acc, lo, hi);
            const float zh = sm[M_BFR + fE] + lo + hi;
            const float ch = cbeta * zh + (1.f - cbeta) * xh;
            const float cc = cm * cx + (1.f - cm) * ch;
            sm[M_CLC + rE * 64 + fE] = cc;
            out[((size_t)(b0 + rE) * Sdim + s) * Fdim + fE] = cc;
            const float d1 = cx - xh, d2 = cx - zh, d3 = cx - ch;
            loss += cm * (d1 * d1 + d2 * d2 + d3 * d3) * cInv;
        }
        __syncthreads();

        // F: gates = gml + clc @ WihClc^T + h @ Whh^T   (k-pair packed)
        {
            u64 A00 = 0ULL, A01 = 0ULL, A02 = 0ULL, A03 = 0ULL;
            u64 A10 = 0ULL, A11 = 0ULL, A12 = 0ULL, A13 = 0ULL;
            const float* clc0 = sm + M_CLC;
            const float* hr0  = sm + M_HR;
#pragma unroll
            for (int q = 0; q < 16; ++q)
                FSTEP(sm + M_WIHQ + (q * 512 + j0) * 4,
                      sm + M_WIHQ + (q * 512 + j1) * 4,
                      clc0 + 4 * q, 64);
#pragma unroll
            for (int q = 0; q < 4; ++q)
                FSTEP(sm + M_WHHR + (q * 512 + j0) * 4,
                      sm + M_WHHR + (q * 512 + j1) * 4,
                      hr0 + 4 * q, 128);
#pragma unroll 7
            for (int q = 0; q < KQ; ++q)
                FSTEP(g_WhhQ + ((size_t)q * 512 + j0) * 4,
                      g_WhhQ + ((size_t)q * 512 + j1) * 4,
                      hr0 + 16 + 4 * q, 128);
            float lo, hi;
            up2(A00, lo, hi); sm[M_GT + 0 * 512 + j0] = lo + hi + cgml[0];
            up2(A01, lo, hi); sm[M_GT + 1 * 512 + j0] = lo + hi + cgml[1];
            up2(A02, lo, hi); sm[M_GT + 2 * 512 + j0] = lo + hi + cgml[2];
            up2(A03, lo, hi); sm[M_GT + 3 * 512 + j0] = lo + hi + cgml[3];
            up2(A10, lo, hi); sm[M_GT + 0 * 512 + j1] = lo + hi + cgml[4];
            up2(A11, lo, hi); sm[M_GT + 1 * 512 + j1] = lo + hi + cgml[5];
            up2(A12, lo, hi); sm[M_GT + 2 * 512 + j1] = lo + hi + cgml[6];
            up2(A13, lo, hi); sm[M_GT + 3 * 512 + j1] = lo + hi + cgml[7];
        }
        __syncthreads();

        // G: LSTM update + apply gamma_h(s+1)
        {
            const float* g0 = sm + M_GT + rG * 512;
            const float iv0 = sigf(g0[jG]);
            const float fv0 = sigf(g0[128 + jG]);
            const float gv0 = tanhf(g0[256 + jG]);
            const float ov0 = sigf(g0[384 + jG]);
            c1 = fv0 * c1 + iv0 * gv0;
            sm[M_HR + rG * 128 + jG] = ov0 * tanhf(c1) * gh1;
            const float* g1 = sm + M_GT + (2 + rG) * 512;
            const float iv1 = sigf(g1[jG]);
            const float fv1 = sigf(g1[128 + jG]);
            const float gv1 = tanhf(g1[256 + jG]);
            const float ov1 = sigf(g1[384 + jG]);
            c2 = fv1 * c2 + iv1 * gv1;
            sm[M_HR + (2 + rG) * 128 + jG] = ov1 * tanhf(c2) * gh2;
        }
        __syncthreads();

        cx = nx; cm = nm; cbeta = nbeta;
#pragma unroll
        for (int r = 0; r < 8; ++r) cgml[r] = ngml[r];
    }

    sm[M_RED + t] = loss;
    __syncthreads();
    for (int off = 128; off > 0; off >>= 1) { if (t < off) sm[M_RED + t] += sm[M_RED + t + off]; __syncthreads(); }
    if (t == 0) g_lossPartial[blockIdx.x] = sm[M_RED];
}

__global__ void rits_loss_final(float* __restrict__ out, int out_size) {
    __shared__ float red[NBLK];
    const int t = threadIdx.x;
    red[t] = g_lossPartial[t];
    __syncthreads();
    for (int off = NBLK / 2; off > 0; off >>= 1) { if (t < off) red[t] += red[t + off]; __syncthreads(); }
    const long long bsf = (long long)Bdim * Sdim * Fdim;
    if (t == 0 && (long long)out_size > bsf) out[bsf] = red[0] / (float)Sdim;
}

extern "C" void kernel_launch(void* const* d_in, const int* in_sizes, int n_in,
                              void* d_out, int out_size) {
    const float* x   = (const float*)d_in[0];
    const float* m   = (const float*)d_in[1];
    const float* tt  = (const float*)d_in[2];
    const float* Wdh = (const float*)d_in[3];
    const float* bdh = (const float*)d_in[4];
    const float* Wdm = (const float*)d_in[5];
    const float* bdm = (const float*)d_in[6];
    const float* Wtr = (const float*)d_in[7];
    const float* btr = (const float*)d_in[8];
    const float* Wfr = (const float*)d_in[9];
    const float* bfr = (const float*)d_in[10];
    const float* Wwc = (const float*)d_in[11];
    const float* bwc = (const float*)d_in[12];
    const float* Wih = (const float*)d_in[13];
    const float* Whh = (const float*)d_in[14];
    const float* bih = (const float*)d_in[15];
    const float* bhh = (const float*)d_in[16];
    float* out = (float*)d_out;

    cudaFuncSetAttribute(rits_gml, cudaFuncAttributeMaxDynamicSharedMemorySize, GML_SMF * 4);
    cudaFuncSetAttribute(rits_main, cudaFuncAttributeMaxDynamicSharedMemorySize, M_SMB);

    rits_denom<<<Sdim, 256>>>(m);
    rits_whhq<<<(KQ * 512 * 4 + 255) / 256, 256>>>(Whh);
    rits_gh<<<1024, 256>>>(tt, Wdh, bdh);
    rits_betak<<<1024, 256>>>(tt, m, Wdm, bdm, Wwc, bwc);
    rits_gml<<<256, 256, GML_SMF * 4>>>(m, Wih, bih, bhh);
    rits_main<<<NBLK, 256, M_SMB>>>(x, m, Wtr, btr, Wfr, bfr, Wih, Whh, out);
    rits_loss_final<<<1, NBLK>>>(out, out_size);
}